// round 13
// baseline (speedup 1.0000x reference)
#include <cuda_runtime.h>
#include <cuda_bf16.h>
#include <float.h>
#include <math.h>
#include <stdint.h>

#define NN 8192
#define DD 128
#define CC 7
#define KNN 5
#define EPSF 1e-6f

#define BM 64
#define BN 64
#define THREADS 256
#define NESLOTS 8                      // j-eighths
#define UTILES 16                      // tiles per unit (NN/8/BN)
#define NUNITS 1024                    // 128 i-tiles * 8 eighths

#define ASTRIDE 272                    // 128 bf16 = 256B + 16B pad

// ---------------- smem map (bytes) ----------------
#define SM_WRK  0                       // int (unit broadcast)
#define SM_CT   16                      // float2 [2][64] = 1024
#define SM_A    1088                    // 17408
#define SM_B    18496                   // 2 stages * 17408
#define SM_BSTG 17408
#define SM_TOTAL 53312
// flush overlay reuses B stage0: 64 rows * 8 slots * 5 floats = 10240 B

// ---------------- device scratch ----------------
__device__ __nv_bfloat16 g_hi[NN * DD];
__device__ float  g_rn[NN];
__device__ float  g_cn[NN];
__device__ float  g_p5[NESLOTS][NN][KNN];
__device__ double g_accCE;
__device__ double g_accPair;
__device__ int    g_work;
__device__ int    g_done;

// ---------------- PTX helpers ----------------
__device__ __forceinline__ uint32_t smem_u32(const void* p) {
    uint32_t a;
    asm("{ .reg .u64 t; cvta.to.shared.u64 t, %1; cvt.u32.u64 %0, t; }" : "=r"(a) : "l"(p));
    return a;
}
__device__ __forceinline__ void cp16(uint32_t s, const void* g) {
    asm volatile("cp.async.cg.shared.global [%0], [%1], 16;" :: "r"(s), "l"(g));
}
#define CP_COMMIT() asm volatile("cp.async.commit_group;" ::: "memory")
#define CP_WAIT0()  asm volatile("cp.async.wait_group 0;" ::: "memory")

__device__ __forceinline__ void ldsm4(uint32_t* r, uint32_t a) {
    asm volatile("ldmatrix.sync.aligned.m8n8.x4.shared.b16 {%0,%1,%2,%3}, [%4];"
                 : "=r"(r[0]), "=r"(r[1]), "=r"(r[2]), "=r"(r[3]) : "r"(a));
}
__device__ __forceinline__ void mma_bf16(float* c, const uint32_t* a, const uint32_t* b) {
    asm volatile("mma.sync.aligned.m16n8k16.row.col.f32.bf16.bf16.f32 "
                 "{%0,%1,%2,%3}, {%4,%5,%6,%7}, {%8,%9}, {%0,%1,%2,%3};"
                 : "+f"(c[0]), "+f"(c[1]), "+f"(c[2]), "+f"(c[3])
                 : "r"(a[0]), "r"(a[1]), "r"(a[2]), "r"(a[3]), "r"(b[0]), "r"(b[1]));
}

#define T5_INSERT(arr, thv, val)                                              \
    do {                                                                      \
        int _mi = 0; float _mv = (arr)[0];                                    \
        _Pragma("unroll")                                                     \
        for (int _k = 1; _k < KNN; _k++)                                      \
            if ((arr)[_k] > _mv) { _mv = (arr)[_k]; _mi = _k; }               \
        _Pragma("unroll")                                                     \
        for (int _k = 0; _k < KNN; _k++) if (_k == _mi) (arr)[_k] = (val);    \
        (thv) = (arr)[0];                                                     \
        _Pragma("unroll")                                                     \
        for (int _k = 1; _k < KNN; _k++) (thv) = fmaxf((thv), (arr)[_k]);     \
    } while (0)

// ---------------- init ----------------
__global__ void k_init() {
    g_accCE = 0.0; g_accPair = 0.0; g_work = 0; g_done = 0;
}

// ---------------- fused convert + norms + CE ----------------
__global__ void k_pre(const float* __restrict__ x, const float* __restrict__ sc,
                      const int* __restrict__ tg) {
    if (blockIdx.x < NN / 8) {
        // convert + norms: 8 rows per block, one warp per row
        int row  = blockIdx.x * 8 + (threadIdx.x >> 5);
        int lane = threadIdx.x & 31;
        float4 v = reinterpret_cast<const float4*>(x + (size_t)row * DD)[lane];
        __nv_bfloat162 h0 = {__float2bfloat16(v.x), __float2bfloat16(v.y)};
        __nv_bfloat162 h1 = {__float2bfloat16(v.z), __float2bfloat16(v.w)};
        uint2 packed = {*reinterpret_cast<uint32_t*>(&h0), *reinterpret_cast<uint32_t*>(&h1)};
        *reinterpret_cast<uint2*>(&g_hi[(size_t)row * DD + lane * 4]) = packed;

        float s  = v.x + v.y + v.z + v.w;
        float n2 = v.x * v.x + v.y * v.y + v.z * v.z + v.w * v.w;
#pragma unroll
        for (int o = 16; o > 0; o >>= 1) {
            s  += __shfl_xor_sync(0xffffffffu, s, o);
            n2 += __shfl_xor_sync(0xffffffffu, n2, o);
        }
        if (lane == 0) {
            g_rn[row] = n2 + 2.0f * EPSF * s + (float)DD * EPSF * EPSF;
            g_cn[row] = n2 - 2.0f * EPSF * s;
        }
    } else {
        // cross entropy: 256 rows per block
        int i = (blockIdx.x - NN / 8) * 256 + threadIdx.x;
        const float* s = sc + (size_t)i * CC;
        float m = s[0];
#pragma unroll
        for (int c = 1; c < CC; c++) m = fmaxf(m, s[c]);
        float sum = 0.f;
#pragma unroll
        for (int c = 0; c < CC; c++) sum += expf(s[c] - m);
        float ce = m + logf(sum) - s[tg[i]];

        __shared__ double sh[256];
        sh[threadIdx.x] = (double)ce;
        __syncthreads();
#pragma unroll
        for (int o = 128; o > 0; o >>= 1) {
            if (threadIdx.x < o) sh[threadIdx.x] += sh[threadIdx.x + o];
            __syncthreads();
        }
        if (threadIdx.x == 0) atomicAdd(&g_accCE, sh[0]);
    }
}

// ---------------- persistent fused GEMM + register top-5 ----------------
__global__ void __launch_bounds__(THREADS, 4)
k_dist(const int* __restrict__ tgt) {
    extern __shared__ char smem[];
    uint32_t smb = smem_u32(smem);
    int tid  = threadIdx.x;
    int lane = tid & 31;
    int w    = tid >> 5;
    int wm   = w >> 1;          // 0..3 : 16-row block
    int wn   = w & 1;           // 0..1 : 32-col block

    int*    sWrk = (int*)(smem + SM_WRK);
    float2* sCT  = (float2*)(smem + SM_CT);   // [2][64]

    int lrow[2];
#pragma unroll
    for (int q = 0; q < 2; q++)
        lrow[q] = wm * 16 + (lane >> 2) + (q << 3);

    uint32_t aOff  = smb + SM_A + (wm * 16 + (lane & 15)) * ASTRIDE + (lane >> 4) * 16;
    uint32_t bRow4 = (wn * 32 + ((lane >> 4) << 3) + (lane & 7)) * ASTRIDE + (((lane >> 3) & 1) << 4);

    int   curA = -1;
    float rnq[2];
    int   tgq[2];

    for (;;) {
        if (tid == 0) sWrk[0] = atomicAdd(&g_work, 1);
        __syncthreads();
        int unit = sWrk[0];
        if (unit >= NUNITS) break;

        int it      = unit >> 3;
        int e       = unit & 7;
        int rowBase = it * BM;
        int jBase0  = e * (NN / NESLOTS);

        // ---- A (re)load ----
        if (it != curA) {
#pragma unroll
            for (int itc = 0; itc < 4; itc++) {
                int q   = itc * THREADS + tid;
                int row = q >> 4;
                int c   = q & 15;
                cp16(smb + SM_A + row * ASTRIDE + c * 16,
                     g_hi + (size_t)(rowBase + row) * DD + c * 8);
            }
            curA = it;
#pragma unroll
            for (int q = 0; q < 2; q++) {
                rnq[q] = g_rn[rowBase + lrow[q]];
                tgq[q] = tgt[rowBase + lrow[q]];
            }
        }
        // ---- B(0) ----
#pragma unroll
        for (int itc = 0; itc < 4; itc++) {
            int q   = itc * THREADS + tid;
            int row = q >> 4;
            int c   = q & 15;
            cp16(smb + SM_B + row * ASTRIDE + c * 16,
                 g_hi + (size_t)(jBase0 + row) * DD + c * 8);
        }
        CP_COMMIT();
        if (tid < BN)
            sCT[tid] = make_float2(g_cn[jBase0 + tid], __int_as_float(tgt[jBase0 + tid]));

        float t5[2][KNN];
        float th[2];
#pragma unroll
        for (int q = 0; q < 2; q++) {
            th[q] = FLT_MAX;
#pragma unroll
            for (int k = 0; k < KNN; k++) t5[q][k] = FLT_MAX;
        }

        for (int u = 0; u < UTILES; u++) {
            float2 nct;
            bool   haveN = (u + 1 < UTILES) && (tid < BN);
            if (haveN) {
                int jb = jBase0 + (u + 1) * BN;
                nct = make_float2(g_cn[jb + tid], __int_as_float(tgt[jb + tid]));
            }

            CP_WAIT0();
            __syncthreads();

            if (u + 1 < UTILES) {
                int jb = jBase0 + (u + 1) * BN;
                uint32_t bs = smb + SM_B + ((u + 1) & 1) * SM_BSTG;
#pragma unroll
                for (int itc = 0; itc < 4; itc++) {
                    int q   = itc * THREADS + tid;
                    int row = q >> 4;
                    int c   = q & 15;
                    cp16(bs + row * ASTRIDE + c * 16,
                         g_hi + (size_t)(jb + row) * DD + c * 8);
                }
                if (haveN) sCT[((u + 1) & 1) * BN + tid] = nct;
            }
            CP_COMMIT();

            // preload cn/tg columns
            float4 ct[4];
            {
                int slot = (u & 1) * BN;
#pragma unroll
                for (int ni = 0; ni < 4; ni++) {
                    int cb = wn * 32 + ni * 8 + 2 * (lane & 3);
                    ct[ni] = *reinterpret_cast<const float4*>(&sCT[slot + cb]);
                }
            }

            // MMA over K=128
            float acc[4][4];
#pragma unroll
            for (int ni = 0; ni < 4; ni++)
#pragma unroll
                for (int q = 0; q < 4; q++) acc[ni][q] = 0.f;

            uint32_t bH = smb + SM_B + (u & 1) * SM_BSTG + bRow4;

#pragma unroll
            for (int kk = 0; kk < 8; kk++) {
                uint32_t ah[4], bh[4][2];
                ldsm4(ah, aOff + kk * 32);
#pragma unroll
                for (int pr = 0; pr < 2; pr++)
                    ldsm4(&bh[pr * 2][0], bH + pr * 16 * ASTRIDE + kk * 32);
#pragma unroll
                for (int ni = 0; ni < 4; ni++)
                    mma_bf16(acc[ni], ah, bh[ni]);
            }

            // register epilogue
            {
                int jb = jBase0 + u * BN;
                int sj[2];
#pragma unroll
                for (int q = 0; q < 2; q++) sj[q] = (rowBase + lrow[q]) - jb;

#pragma unroll
                for (int ni = 0; ni < 4; ni++) {
                    int cb = wn * 32 + ni * 8 + 2 * (lane & 3);
                    float cn0 = ct[ni].x, cn1 = ct[ni].z;
                    int   tg0 = __float_as_int(ct[ni].y), tg1 = __float_as_int(ct[ni].w);
#pragma unroll
                    for (int q = 0; q < 2; q++) {
                        float d2a = fmaf(-2.0f, acc[ni][2 * q],     rnq[q] + cn0);
                        float d2b = fmaf(-2.0f, acc[ni][2 * q + 1], rnq[q] + cn1);
                        if (d2a < th[q] && tg0 == tgq[q] && cb != sj[q])
                            T5_INSERT(t5[q], th[q], d2a);
                        if (d2b < th[q] && tg1 == tgq[q] && (cb + 1) != sj[q])
                            T5_INSERT(t5[q], th[q], d2b);
                    }
                }
            }
        }

        // ---- flush unit partials: 8 per row -> g_p5[e] ----
        __syncthreads();
        float* M = (float*)(smem + SM_B);      // overlay (B drained)
        int slot8 = wn * 4 + (lane & 3);
#pragma unroll
        for (int q = 0; q < 2; q++)
#pragma unroll
            for (int k = 0; k < KNN; k++)
                M[(lrow[q] * 8 + slot8) * KNN + k] = t5[q][k];
        __syncthreads();

        if (tid < BM) {
            const float* mrow = M + tid * 8 * KNN;
            float best[KNN], bth = FLT_MAX;
#pragma unroll
            for (int k = 0; k < KNN; k++) best[k] = FLT_MAX;
#pragma unroll
            for (int j = 0; j < 8 * KNN; j++) {
                float v = mrow[j];
                if (v < bth) T5_INSERT(best, bth, v);
            }
#pragma unroll
            for (int k = 0; k < KNN; k++) g_p5[e][rowBase + tid][k] = best[k];
        }
        __syncthreads();   // protect overlay before next unit's B(0)
    }
}

// ---------------- merge + pair sum + finalize (atomic ticket) ----------------
#define MF_BLOCKS (NN / 256)
__global__ void k_mf(float* out) {
    int i = blockIdx.x * blockDim.x + threadIdx.x;
    float best[KNN], bth = FLT_MAX;
#pragma unroll
    for (int k = 0; k < KNN; k++) best[k] = FLT_MAX;
#pragma unroll
    for (int e = 0; e < NESLOTS; e++)
#pragma unroll
        for (int k = 0; k < KNN; k++) {
            float v = g_p5[e][i][k];
            if (v < bth) T5_INSERT(best, bth, v);
        }
    float sum = 0.f;
#pragma unroll
    for (int k = 0; k < KNN; k++)
        if (best[k] < 1e37f) sum += best[k];

    __shared__ double sh[256];
    sh[threadIdx.x] = (double)sum / (double)DD;
    __syncthreads();
#pragma unroll
    for (int o = 128; o > 0; o >>= 1) {
        if (threadIdx.x < o) sh[threadIdx.x] += sh[threadIdx.x + o];
        __syncthreads();
    }
    if (threadIdx.x == 0) {
        atomicAdd(&g_accPair, sh[0]);
        __threadfence();
        int t = atomicAdd(&g_done, 1);
        if (t == MF_BLOCKS - 1) {
            double ce   = atomicAdd(&g_accCE, 0.0);
            double pair = atomicAdd(&g_accPair, 0.0);
            out[0] = (float)(ce / (double)NN + (0.5 / (double)KNN) * pair);
        }
    }
}

// ---------------- launch ----------------
extern "C" void kernel_launch(void* const* d_in, const int* in_sizes, int n_in,
                              void* d_out, int out_size) {
    const float* x  = nullptr;
    const float* sc = nullptr;
    const int*   tg = nullptr;
    for (int i = 0; i < n_in; i++) {
        if (in_sizes[i] == NN * DD)      x  = (const float*)d_in[i];
        else if (in_sizes[i] == NN * CC) sc = (const float*)d_in[i];
        else if (in_sizes[i] == NN)      tg = (const int*)d_in[i];
    }
    float* out = (float*)d_out;

    static int sms = 0;
    if (!sms) {
        int dev = 0;
        cudaGetDevice(&dev);
        cudaDeviceGetAttribute(&sms, cudaDevAttrMultiProcessorCount, dev);
        cudaFuncSetAttribute(k_dist, cudaFuncAttributeMaxDynamicSharedMemorySize, SM_TOTAL);
    }
    int grid = sms * 4;
    if (grid > NUNITS) grid = NUNITS;

    k_init<<<1, 1>>>();
    k_pre<<<NN / 8 + NN / 256, 256>>>(x, sc, tg);
    k_dist<<<grid, THREADS, SM_TOTAL>>>(tg);
    k_mf<<<MF_BLOCKS, 256>>>(out);
}

// round 14
// speedup vs baseline: 1.0431x; 1.0431x over previous
#include <cuda_runtime.h>
#include <cuda_bf16.h>
#include <float.h>
#include <math.h>
#include <stdint.h>

#define NN 8192
#define DD 128
#define CC 7
#define KNN 5
#define EPSF 1e-6f

#define BM 64
#define BN 64
#define THREADS 256
#define JQUARTERS 4
#define JTILES (NN / JQUARTERS / BN)   // 32 j-tiles per CTA
#define ITILES (NN / BM)               // 128 i-tiles

#define ASTRIDE 272                    // 128 bf16 = 256B + 16B pad

// ---------------- smem map (bytes) ----------------
#define SM_CT   0                       // float2 [2][64]  (cn, tg-bits)
#define SM_A    1024                    // 64 * 272 = 17408
#define SM_B    18432                   // 2 stages * 17408
#define SM_BSTG 17408
#define SM_TOTAL 53248
// merge overlay reuses B region: 64 rows * 8 slots * 5 floats = 10240 B

// ---------------- device scratch ----------------
__device__ __nv_bfloat16 g_hi[NN * DD];
__device__ float  g_rn[NN];
__device__ float  g_cn[NN];
__device__ float  g_part5[JQUARTERS][NN][KNN];
__device__ double g_accCE;
__device__ double g_accPair;
__device__ int    g_done;

// ---------------- PTX helpers ----------------
__device__ __forceinline__ uint32_t smem_u32(const void* p) {
    uint32_t a;
    asm("{ .reg .u64 t; cvta.to.shared.u64 t, %1; cvt.u32.u64 %0, t; }" : "=r"(a) : "l"(p));
    return a;
}
__device__ __forceinline__ void cp16(uint32_t s, const void* g) {
    asm volatile("cp.async.cg.shared.global [%0], [%1], 16;" :: "r"(s), "l"(g));
}
#define CP_COMMIT() asm volatile("cp.async.commit_group;" ::: "memory")
#define CP_WAIT0()  asm volatile("cp.async.wait_group 0;" ::: "memory")

__device__ __forceinline__ void ldsm4(uint32_t* r, uint32_t a) {
    asm volatile("ldmatrix.sync.aligned.m8n8.x4.shared.b16 {%0,%1,%2,%3}, [%4];"
                 : "=r"(r[0]), "=r"(r[1]), "=r"(r[2]), "=r"(r[3]) : "r"(a));
}
__device__ __forceinline__ void mma_bf16(float* c, const uint32_t* a, const uint32_t* b) {
    asm volatile("mma.sync.aligned.m16n8k16.row.col.f32.bf16.bf16.f32 "
                 "{%0,%1,%2,%3}, {%4,%5,%6,%7}, {%8,%9}, {%0,%1,%2,%3};"
                 : "+f"(c[0]), "+f"(c[1]), "+f"(c[2]), "+f"(c[3])
                 : "r"(a[0]), "r"(a[1]), "r"(a[2]), "r"(a[3]), "r"(b[0]), "r"(b[1]));
}

#define T5_INSERT(arr, thv, val)                                              \
    do {                                                                      \
        int _mi = 0; float _mv = (arr)[0];                                    \
        _Pragma("unroll")                                                     \
        for (int _k = 1; _k < KNN; _k++)                                      \
            if ((arr)[_k] > _mv) { _mv = (arr)[_k]; _mi = _k; }               \
        _Pragma("unroll")                                                     \
        for (int _k = 0; _k < KNN; _k++) if (_k == _mi) (arr)[_k] = (val);    \
        (thv) = (arr)[0];                                                     \
        _Pragma("unroll")                                                     \
        for (int _k = 1; _k < KNN; _k++) (thv) = fmaxf((thv), (arr)[_k]);     \
    } while (0)

// ---------------- init ----------------
__global__ void k_init() { g_accCE = 0.0; g_accPair = 0.0; g_done = 0; }

// ---------------- fused convert + norms + CE ----------------
__global__ void k_pre(const float* __restrict__ x, const float* __restrict__ sc,
                      const int* __restrict__ tg) {
    if (blockIdx.x < NN / 8) {
        int row  = blockIdx.x * 8 + (threadIdx.x >> 5);
        int lane = threadIdx.x & 31;
        float4 v = reinterpret_cast<const float4*>(x + (size_t)row * DD)[lane];
        __nv_bfloat162 h0 = {__float2bfloat16(v.x), __float2bfloat16(v.y)};
        __nv_bfloat162 h1 = {__float2bfloat16(v.z), __float2bfloat16(v.w)};
        uint2 packed = {*reinterpret_cast<uint32_t*>(&h0), *reinterpret_cast<uint32_t*>(&h1)};
        *reinterpret_cast<uint2*>(&g_hi[(size_t)row * DD + lane * 4]) = packed;

        float s  = v.x + v.y + v.z + v.w;
        float n2 = v.x * v.x + v.y * v.y + v.z * v.z + v.w * v.w;
#pragma unroll
        for (int o = 16; o > 0; o >>= 1) {
            s  += __shfl_xor_sync(0xffffffffu, s, o);
            n2 += __shfl_xor_sync(0xffffffffu, n2, o);
        }
        if (lane == 0) {
            g_rn[row] = n2 + 2.0f * EPSF * s + (float)DD * EPSF * EPSF;
            g_cn[row] = n2 - 2.0f * EPSF * s;
        }
    } else {
        int i = (blockIdx.x - NN / 8) * 256 + threadIdx.x;
        const float* s = sc + (size_t)i * CC;
        float m = s[0];
#pragma unroll
        for (int c = 1; c < CC; c++) m = fmaxf(m, s[c]);
        float sum = 0.f;
#pragma unroll
        for (int c = 0; c < CC; c++) sum += expf(s[c] - m);
        float ce = m + logf(sum) - s[tg[i]];

        __shared__ double sh[256];
        sh[threadIdx.x] = (double)ce;
        __syncthreads();
#pragma unroll
        for (int o = 128; o > 0; o >>= 1) {
            if (threadIdx.x < o) sh[threadIdx.x] += sh[threadIdx.x + o];
            __syncthreads();
        }
        if (threadIdx.x == 0) atomicAdd(&g_accCE, sh[0]);
    }
}

// ---------------- fused bf16 mma.sync GEMM + register top-5 (R12-verified) ----------------
__global__ void __launch_bounds__(THREADS, 4)
k_dist(const int* __restrict__ tgt) {
    extern __shared__ char smem[];
    uint32_t smb = smem_u32(smem);
    int tid  = threadIdx.x;
    int lane = tid & 31;
    int w    = tid >> 5;
    int wm   = w >> 1;          // 0..3 : 16-row block
    int wn   = w & 1;           // 0..1 : 32-col block

    int it      = blockIdx.x >> 2;
    int jq      = blockIdx.x & 3;
    int rowBase = it * BM;
    int jBase0  = jq * (NN / JQUARTERS);

    float2* sCT = (float2*)(smem + SM_CT);   // [2][64] : {cn, tg-bits}

    // ---- prologue: A + B(0) in one group ----
#pragma unroll
    for (int itc = 0; itc < 4; itc++) {
        int q   = itc * THREADS + tid;
        int row = q >> 4;
        int c   = q & 15;
        cp16(smb + SM_A + row * ASTRIDE + c * 16,
             g_hi + (size_t)(rowBase + row) * DD + c * 8);
    }
#pragma unroll
    for (int itc = 0; itc < 4; itc++) {
        int q   = itc * THREADS + tid;
        int row = q >> 4;
        int c   = q & 15;
        cp16(smb + SM_B + row * ASTRIDE + c * 16,
             g_hi + (size_t)(jBase0 + row) * DD + c * 8);
    }
    CP_COMMIT();
    if (tid < BN)
        sCT[tid] = make_float2(g_cn[jBase0 + tid], __int_as_float(tgt[jBase0 + tid]));

    // ---- per-thread row state: 2 rows ----
    int   lrow[2];
    float rnq[2];
    int   tgq[2];
#pragma unroll
    for (int q = 0; q < 2; q++) {
        lrow[q] = wm * 16 + (lane >> 2) + (q << 3);
        rnq[q]  = g_rn[rowBase + lrow[q]];
        tgq[q]  = tgt[rowBase + lrow[q]];
    }
    float t5[2][KNN];
    float th[2];
#pragma unroll
    for (int q = 0; q < 2; q++) {
        th[q] = FLT_MAX;
#pragma unroll
        for (int k = 0; k < KNN; k++) t5[q][k] = FLT_MAX;
    }

    uint32_t aOff  = smb + SM_A + (wm * 16 + (lane & 15)) * ASTRIDE + (lane >> 4) * 16;
    uint32_t bRow4 = (wn * 32 + ((lane >> 4) << 3) + (lane & 7)) * ASTRIDE + (((lane >> 3) & 1) << 4);

    for (int u = 0; u < JTILES; u++) {
        float2 nct;
        bool   haveN = (u + 1 < JTILES) && (tid < BN);
        if (haveN) {
            int jb = jBase0 + (u + 1) * BN;
            nct = make_float2(g_cn[jb + tid], __int_as_float(tgt[jb + tid]));
        }

        CP_WAIT0();
        __syncthreads();

        if (u + 1 < JTILES) {
            int jb = jBase0 + (u + 1) * BN;
            uint32_t bs = smb + SM_B + ((u + 1) & 1) * SM_BSTG;
#pragma unroll
            for (int itc = 0; itc < 4; itc++) {
                int q   = itc * THREADS + tid;
                int row = q >> 4;
                int c   = q & 15;
                cp16(bs + row * ASTRIDE + c * 16,
                     g_hi + (size_t)(jb + row) * DD + c * 8);
            }
            if (haveN) sCT[((u + 1) & 1) * BN + tid] = nct;
        }
        CP_COMMIT();

        float4 ct[4];
        {
            int slot = (u & 1) * BN;
#pragma unroll
            for (int ni = 0; ni < 4; ni++) {
                int cb = wn * 32 + ni * 8 + 2 * (lane & 3);
                ct[ni] = *reinterpret_cast<const float4*>(&sCT[slot + cb]);
            }
        }

        float acc[4][4];
#pragma unroll
        for (int ni = 0; ni < 4; ni++)
#pragma unroll
            for (int q = 0; q < 4; q++) acc[ni][q] = 0.f;

        uint32_t bH = smb + SM_B + (u & 1) * SM_BSTG + bRow4;

#pragma unroll
        for (int kk = 0; kk < 8; kk++) {
            uint32_t ah[4], bh[4][2];
            ldsm4(ah, aOff + kk * 32);
#pragma unroll
            for (int pr = 0; pr < 2; pr++)
                ldsm4(&bh[pr * 2][0], bH + pr * 16 * ASTRIDE + kk * 32);
#pragma unroll
            for (int ni = 0; ni < 4; ni++)
                mma_bf16(acc[ni], ah, bh[ni]);
        }

        {
            int jb = jBase0 + u * BN;
            int sj[2];
#pragma unroll
            for (int q = 0; q < 2; q++) sj[q] = (rowBase + lrow[q]) - jb;

#pragma unroll
            for (int ni = 0; ni < 4; ni++) {
                int cb = wn * 32 + ni * 8 + 2 * (lane & 3);
                float cn0 = ct[ni].x, cn1 = ct[ni].z;
                int   tg0 = __float_as_int(ct[ni].y), tg1 = __float_as_int(ct[ni].w);
#pragma unroll
                for (int q = 0; q < 2; q++) {
                    float d2a = fmaf(-2.0f, acc[ni][2 * q],     rnq[q] + cn0);
                    float d2b = fmaf(-2.0f, acc[ni][2 * q + 1], rnq[q] + cn1);
                    if (d2a < th[q] && tg0 == tgq[q] && cb != sj[q])
                        T5_INSERT(t5[q], th[q], d2a);
                    if (d2b < th[q] && tg1 == tgq[q] && (cb + 1) != sj[q])
                        T5_INSERT(t5[q], th[q], d2b);
                }
            }
        }
    }

    // ---- in-CTA merge: 8 partials per row ----
    __syncthreads();
    float* M = (float*)(smem + SM_B);      // overlay, 10240 B
    int slot8 = wn * 4 + (lane & 3);
#pragma unroll
    for (int q = 0; q < 2; q++)
#pragma unroll
        for (int k = 0; k < KNN; k++)
            M[(lrow[q] * 8 + slot8) * KNN + k] = t5[q][k];
    __syncthreads();

    if (tid < BM) {
        const float* mrow = M + tid * 8 * KNN;
        float best[KNN], bth = FLT_MAX;
#pragma unroll
        for (int k = 0; k < KNN; k++) best[k] = FLT_MAX;
#pragma unroll
        for (int j = 0; j < 8 * KNN; j++) {
            float v = mrow[j];
            if (v < bth) T5_INSERT(best, bth, v);
        }
#pragma unroll
        for (int k = 0; k < KNN; k++) g_part5[jq][rowBase + tid][k] = best[k];
    }
}

// ---------------- merge + pair sum + finalize (2 threads/row, atomic ticket) ----------------
#define MF_BLOCKS 128
__global__ void k_mf(float* out) {
    int gt   = blockIdx.x * blockDim.x + threadIdx.x;   // 16384 threads
    int i    = gt >> 1;                                  // row
    int half = gt & 1;                                   // slots [0,1] or [2,3]

    float best[KNN], bth = FLT_MAX;
#pragma unroll
    for (int k = 0; k < KNN; k++) best[k] = FLT_MAX;
#pragma unroll
    for (int sp = 0; sp < 2; sp++)
#pragma unroll
        for (int k = 0; k < KNN; k++) {
            float v = g_part5[half * 2 + sp][i][k];
            if (v < bth) T5_INSERT(best, bth, v);
        }

    // exchange partner's 5 values via shfl (partner = lane^1)
    float sum = 0.f;
    {
        float merged[2 * KNN];
#pragma unroll
        for (int k = 0; k < KNN; k++) {
            merged[k]       = best[k];
            merged[KNN + k] = __shfl_xor_sync(0xffffffffu, best[k], 1);
        }
        float f5[KNN], fth = FLT_MAX;
#pragma unroll
        for (int k = 0; k < KNN; k++) f5[k] = FLT_MAX;
#pragma unroll
        for (int j = 0; j < 2 * KNN; j++) {
            float v = merged[j];
            if (v < fth) T5_INSERT(f5, fth, v);
        }
#pragma unroll
        for (int k = 0; k < KNN; k++)
            if (f5[k] < 1e37f) sum += f5[k];
    }
    if (half) sum = 0.f;     // only even lane of each pair contributes

    __shared__ double sh[128];
    sh[threadIdx.x] = (double)sum / (double)DD;
    __syncthreads();
#pragma unroll
    for (int o = 64; o > 0; o >>= 1) {
        if (threadIdx.x < o) sh[threadIdx.x] += sh[threadIdx.x + o];
        __syncthreads();
    }
    if (threadIdx.x == 0) {
        atomicAdd(&g_accPair, sh[0]);
        __threadfence();
        int t = atomicAdd(&g_done, 1);
        if (t == MF_BLOCKS - 1) {
            double ce   = atomicAdd(&g_accCE, 0.0);
            double pair = atomicAdd(&g_accPair, 0.0);
            out[0] = (float)(ce / (double)NN + (0.5 / (double)KNN) * pair);
        }
    }
}

// ---------------- launch ----------------
extern "C" void kernel_launch(void* const* d_in, const int* in_sizes, int n_in,
                              void* d_out, int out_size) {
    const float* x  = nullptr;
    const float* sc = nullptr;
    const int*   tg = nullptr;
    for (int i = 0; i < n_in; i++) {
        if (in_sizes[i] == NN * DD)      x  = (const float*)d_in[i];
        else if (in_sizes[i] == NN * CC) sc = (const float*)d_in[i];
        else if (in_sizes[i] == NN)      tg = (const int*)d_in[i];
    }
    float* out = (float*)d_out;

    cudaFuncSetAttribute(k_dist, cudaFuncAttributeMaxDynamicSharedMemorySize, SM_TOTAL);

    k_init<<<1, 1>>>();
    k_pre<<<NN / 8 + NN / 256, 256>>>(x, sc, tg);
    k_dist<<<ITILES * JQUARTERS, THREADS, SM_TOTAL>>>(tg);
    k_mf<<<MF_BLOCKS, 128>>>(out);
}